// round 1
// baseline (speedup 1.0000x reference)
#include <cuda_runtime.h>
#include <cstdint>

// ---------------------------------------------------------------------------
// Problem constants
// ---------------------------------------------------------------------------
#define N_WORD   30000
#define N_TOPIC  1000
#define N_DOC    15000
#define D_IN     300
#define D_OUT    128

#define E_WW 800000
#define E_WT 400000
#define E_WD 600000
#define E_TD 300000
#define E_TT 150000
// etype ids: 0=ww, 1=wt, 2=wd, 3=td, 4=tt

// ---------------------------------------------------------------------------
// Static device scratch (no allocation allowed)
// ---------------------------------------------------------------------------
__device__ float g_Wh_ww[(size_t)N_WORD  * D_OUT];
__device__ float g_Wh_wt[(size_t)N_WORD  * D_OUT];
__device__ float g_Wh_wd[(size_t)N_WORD  * D_OUT];
__device__ float g_Wh_td[(size_t)N_TOPIC * D_OUT];
__device__ float g_Wh_tt[(size_t)N_TOPIC * D_OUT];

__device__ int g_deg_ww[N_WORD];  __device__ int g_off_ww[N_WORD + 1];  __device__ int g_cur_ww[N_WORD];
__device__ int g_deg_wt[N_TOPIC]; __device__ int g_off_wt[N_TOPIC + 1]; __device__ int g_cur_wt[N_TOPIC];
__device__ int g_deg_wd[N_DOC];   __device__ int g_off_wd[N_DOC + 1];   __device__ int g_cur_wd[N_DOC];
__device__ int g_deg_td[N_DOC];   __device__ int g_off_td[N_DOC + 1];   __device__ int g_cur_td[N_DOC];
__device__ int g_deg_tt[N_TOPIC]; __device__ int g_off_tt[N_TOPIC + 1]; __device__ int g_cur_tt[N_TOPIC];

__device__ int   g_ssrc_ww[E_WW]; __device__ float g_sw_ww[E_WW];
__device__ int   g_ssrc_wt[E_WT]; __device__ float g_sw_wt[E_WT];
__device__ int   g_ssrc_wd[E_WD]; __device__ float g_sw_wd[E_WD];
__device__ int   g_ssrc_td[E_TD]; __device__ float g_sw_td[E_TD];
__device__ int   g_ssrc_tt[E_TT]; __device__ float g_sw_tt[E_TT];

// Switch-based accessors (safe everywhere; avoids device-scope pointer init)
__device__ __forceinline__ float* Wh_ptr(int et) {
    switch (et) { case 0: return g_Wh_ww; case 1: return g_Wh_wt; case 2: return g_Wh_wd;
                  case 3: return g_Wh_td; default: return g_Wh_tt; }
}
__device__ __forceinline__ int* deg_ptr(int et) {
    switch (et) { case 0: return g_deg_ww; case 1: return g_deg_wt; case 2: return g_deg_wd;
                  case 3: return g_deg_td; default: return g_deg_tt; }
}
__device__ __forceinline__ int* off_ptr(int et) {
    switch (et) { case 0: return g_off_ww; case 1: return g_off_wt; case 2: return g_off_wd;
                  case 3: return g_off_td; default: return g_off_tt; }
}
__device__ __forceinline__ int* cur_ptr(int et) {
    switch (et) { case 0: return g_cur_ww; case 1: return g_cur_wt; case 2: return g_cur_wd;
                  case 3: return g_cur_td; default: return g_cur_tt; }
}
__device__ __forceinline__ int* ssrc_ptr(int et) {
    switch (et) { case 0: return g_ssrc_ww; case 1: return g_ssrc_wt; case 2: return g_ssrc_wd;
                  case 3: return g_ssrc_td; default: return g_ssrc_tt; }
}
__device__ __forceinline__ float* sw_ptr(int et) {
    switch (et) { case 0: return g_sw_ww; case 1: return g_sw_wt; case 2: return g_sw_wd;
                  case 3: return g_sw_td; default: return g_sw_tt; }
}
__device__ __forceinline__ int ndst_of(int et) {
    switch (et) { case 0: return N_WORD; case 1: return N_TOPIC; case 2: return N_DOC;
                  case 3: return N_DOC; default: return N_TOPIC; }
}

// ---------------------------------------------------------------------------
// Kernel 1: zero degree arrays (all 5 etypes; blockIdx.y = etype)
// ---------------------------------------------------------------------------
__global__ void zero_deg_kernel() {
    int et = blockIdx.y;
    int n = ndst_of(et);
    int i = blockIdx.x * blockDim.x + threadIdx.x;
    if (i < n) deg_ptr(et)[i] = 0;
}

// ---------------------------------------------------------------------------
// Kernel 2: histogram of destination degrees
// ---------------------------------------------------------------------------
__global__ void hist_kernel(const int* __restrict__ dst, int et, int E) {
    int* deg = deg_ptr(et);
    for (int i = blockIdx.x * blockDim.x + threadIdx.x; i < E; i += gridDim.x * blockDim.x)
        atomicAdd(&deg[dst[i]], 1);
}

// ---------------------------------------------------------------------------
// Kernel 3: single-block exclusive scan -> offsets + cursors
// ---------------------------------------------------------------------------
__global__ void scan_kernel(int et) {
    const int n = ndst_of(et);
    int* deg = deg_ptr(et);
    int* off = off_ptr(et);
    int* cur = cur_ptr(et);
    __shared__ int partial[1024];
    int t = threadIdx.x;
    int chunk = (n + 1023) >> 10;
    int beg = t * chunk;
    int end = min(beg + chunk, n);
    int s = 0;
    for (int i = beg; i < end; i++) s += deg[i];
    partial[t] = s;
    __syncthreads();
    // Hillis-Steele inclusive scan over 1024 partials
    for (int d = 1; d < 1024; d <<= 1) {
        int v = (t >= d) ? partial[t - d] : 0;
        __syncthreads();
        partial[t] += v;
        __syncthreads();
    }
    int run = (t == 0) ? 0 : partial[t - 1];
    for (int i = beg; i < end; i++) {
        off[i] = run; cur[i] = run;
        run += deg[i];
    }
    if (t == 1023) off[n] = partial[1023];
}

// ---------------------------------------------------------------------------
// Kernel 4: fill dst-sorted (src, w) pairs
// ---------------------------------------------------------------------------
__global__ void fill_kernel(const int* __restrict__ src, const int* __restrict__ dst,
                            const float* __restrict__ w, int et, int E) {
    int*   cur  = cur_ptr(et);
    int*   ssrc = ssrc_ptr(et);
    float* swt  = sw_ptr(et);
    for (int i = blockIdx.x * blockDim.x + threadIdx.x; i < E; i += gridDim.x * blockDim.x) {
        int slot = atomicAdd(&cur[dst[i]], 1);
        ssrc[slot] = src[i];
        swt[slot]  = w[i];
    }
}

// ---------------------------------------------------------------------------
// Kernel 5: fp32 GEMM  C[M,128] = A[M,K] @ W[K,128] + b
// Block: 256 threads, tile 128x128, 8x8 per thread, K-chunk 16.
// ---------------------------------------------------------------------------
__global__ void __launch_bounds__(256, 2)
gemm_kernel(const float* __restrict__ A, const float* __restrict__ W,
            const float* __restrict__ bias, int et, int M, int K) {
    float* C = Wh_ptr(et);
    __shared__ float As[16][132];   // transposed: As[k][m]
    __shared__ float Bs[16][132];   // Bs[k][n]
    const int tid  = threadIdx.x;
    const int row0 = blockIdx.x * 128;
    const int ty   = tid >> 4;   // 0..15 -> row group
    const int tx   = tid & 15;   // 0..15 -> col group

    float acc[8][8];
#pragma unroll
    for (int i = 0; i < 8; i++)
#pragma unroll
        for (int j = 0; j < 8; j++) acc[i][j] = 0.0f;

    for (int k0 = 0; k0 < K; k0 += 16) {
        // ---- load A tile (128 rows x 16 k), transpose into As[k][m]
#pragma unroll
        for (int i = 0; i < 2; i++) {
            int slot = tid * 2 + i;        // 0..511
            int r  = slot >> 2;            // 0..127
            int kq = slot & 3;             // 0..3 (float4 along k)
            int gr = row0 + r, gk = k0 + kq * 4;
            float4 v = make_float4(0.f, 0.f, 0.f, 0.f);
            if (gr < M) {
                if (gk + 4 <= K) {
                    v = *(const float4*)(A + (size_t)gr * K + gk);
                } else {
                    float t0 = (gk + 0 < K) ? A[(size_t)gr * K + gk + 0] : 0.f;
                    float t1 = (gk + 1 < K) ? A[(size_t)gr * K + gk + 1] : 0.f;
                    float t2 = (gk + 2 < K) ? A[(size_t)gr * K + gk + 2] : 0.f;
                    float t3 = (gk + 3 < K) ? A[(size_t)gr * K + gk + 3] : 0.f;
                    v = make_float4(t0, t1, t2, t3);
                }
            }
            As[kq * 4 + 0][r] = v.x;
            As[kq * 4 + 1][r] = v.y;
            As[kq * 4 + 2][r] = v.z;
            As[kq * 4 + 3][r] = v.w;
        }
        // ---- load B tile (16 k x 128 n)
#pragma unroll
        for (int i = 0; i < 2; i++) {
            int slot = tid * 2 + i;        // 0..511
            int kk = slot >> 5;            // 0..15
            int cq = slot & 31;            // 0..31 (float4 along n)
            int gk = k0 + kk;
            float4 v = make_float4(0.f, 0.f, 0.f, 0.f);
            if (gk < K) v = *(const float4*)(W + (size_t)gk * D_OUT + cq * 4);
            *(float4*)&Bs[kk][cq * 4] = v;
        }
        __syncthreads();
#pragma unroll
        for (int kk = 0; kk < 16; kk++) {
            float a[8], bf[8];
            *(float4*)&a[0]  = *(const float4*)&As[kk][ty * 8];
            *(float4*)&a[4]  = *(const float4*)&As[kk][ty * 8 + 4];
            *(float4*)&bf[0] = *(const float4*)&Bs[kk][tx * 8];
            *(float4*)&bf[4] = *(const float4*)&Bs[kk][tx * 8 + 4];
#pragma unroll
            for (int i = 0; i < 8; i++)
#pragma unroll
                for (int j = 0; j < 8; j++)
                    acc[i][j] = fmaf(a[i], bf[j], acc[i][j]);
        }
        __syncthreads();
    }

    float bb[8];
#pragma unroll
    for (int j = 0; j < 8; j++) bb[j] = bias[tx * 8 + j];
#pragma unroll
    for (int i = 0; i < 8; i++) {
        int r = row0 + ty * 8 + i;
        if (r < M) {
            float4 o0 = make_float4(acc[i][0] + bb[0], acc[i][1] + bb[1],
                                    acc[i][2] + bb[2], acc[i][3] + bb[3]);
            float4 o1 = make_float4(acc[i][4] + bb[4], acc[i][5] + bb[5],
                                    acc[i][6] + bb[6], acc[i][7] + bb[7]);
            *(float4*)(C + (size_t)r * D_OUT + tx * 8)     = o0;
            *(float4*)(C + (size_t)r * D_OUT + tx * 8 + 4) = o1;
        }
    }
}

// ---------------------------------------------------------------------------
// Kernel 6: gather-based mean aggregation.
// One warp per dst node; lane owns float4 of the 128-dim feature.
// etB < 0 -> single etype (word). Otherwise out = mean(etA) + mean(etB).
// ---------------------------------------------------------------------------
__device__ __forceinline__ void seg_mean_acc(int et, int d, int lane, float4& res) {
    const int*   off = off_ptr(et);
    const int*   ss  = ssrc_ptr(et);
    const float* sw  = sw_ptr(et);
    const float* Wh  = Wh_ptr(et);
    int beg = off[d], end = off[d + 1];
    float4 acc0 = make_float4(0.f, 0.f, 0.f, 0.f);
    float4 acc1 = make_float4(0.f, 0.f, 0.f, 0.f);
    int j = beg;
    for (; j + 4 <= end; j += 4) {
        int   s0 = ss[j],   s1 = ss[j+1], s2 = ss[j+2], s3 = ss[j+3];
        float w0 = sw[j],   w1 = sw[j+1], w2 = sw[j+2], w3 = sw[j+3];
        float4 v0 = *(const float4*)(Wh + (size_t)s0 * D_OUT + lane * 4);
        float4 v1 = *(const float4*)(Wh + (size_t)s1 * D_OUT + lane * 4);
        float4 v2 = *(const float4*)(Wh + (size_t)s2 * D_OUT + lane * 4);
        float4 v3 = *(const float4*)(Wh + (size_t)s3 * D_OUT + lane * 4);
        acc0.x = fmaf(w0, v0.x, acc0.x); acc0.y = fmaf(w0, v0.y, acc0.y);
        acc0.z = fmaf(w0, v0.z, acc0.z); acc0.w = fmaf(w0, v0.w, acc0.w);
        acc1.x = fmaf(w1, v1.x, acc1.x); acc1.y = fmaf(w1, v1.y, acc1.y);
        acc1.z = fmaf(w1, v1.z, acc1.z); acc1.w = fmaf(w1, v1.w, acc1.w);
        acc0.x = fmaf(w2, v2.x, acc0.x); acc0.y = fmaf(w2, v2.y, acc0.y);
        acc0.z = fmaf(w2, v2.z, acc0.z); acc0.w = fmaf(w2, v2.w, acc0.w);
        acc1.x = fmaf(w3, v3.x, acc1.x); acc1.y = fmaf(w3, v3.y, acc1.y);
        acc1.z = fmaf(w3, v3.z, acc1.z); acc1.w = fmaf(w3, v3.w, acc1.w);
    }
    for (; j < end; j++) {
        int   s = ss[j];
        float w = sw[j];
        float4 v = *(const float4*)(Wh + (size_t)s * D_OUT + lane * 4);
        acc0.x = fmaf(w, v.x, acc0.x); acc0.y = fmaf(w, v.y, acc0.y);
        acc0.z = fmaf(w, v.z, acc0.z); acc0.w = fmaf(w, v.w, acc0.w);
    }
    float inv = 1.0f / fmaxf((float)(end - beg), 1.0f);
    res.x += (acc0.x + acc1.x) * inv;
    res.y += (acc0.y + acc1.y) * inv;
    res.z += (acc0.z + acc1.z) * inv;
    res.w += (acc0.w + acc1.w) * inv;
}

__global__ void agg_kernel(float* __restrict__ out, int etA, int etB, int n_dst) {
    int warp = (blockIdx.x * blockDim.x + threadIdx.x) >> 5;
    int lane = threadIdx.x & 31;
    if (warp >= n_dst) return;
    float4 res = make_float4(0.f, 0.f, 0.f, 0.f);
    seg_mean_acc(etA, warp, lane, res);
    if (etB >= 0) seg_mean_acc(etB, warp, lane, res);
    *(float4*)(out + (size_t)warp * D_OUT + lane * 4) = res;
}

// ---------------------------------------------------------------------------
// Launch
// ---------------------------------------------------------------------------
extern "C" void kernel_launch(void* const* d_in, const int* in_sizes, int n_in,
                              void* d_out, int out_size) {
    (void)out_size;
    static const int E_arr[5]    = {E_WW, E_WT, E_WD, E_TD, E_TT};
    static const int NDST_arr[5] = {N_WORD, N_TOPIC, N_DOC, N_DOC, N_TOPIC};

    // Resolve input ordering: interleaved (setup_inputs dict order) vs
    // edges-first (reference signature order). W matrices are 38400 elems.
    int iS[5], iD[5], iW_[5], iWm[5], iB[5];
    bool interleaved = (n_in >= 7 && in_sizes[5] == D_IN * D_OUT);
    for (int et = 0; et < 5; et++) {
        if (interleaved) {
            int base = 2 + et * 5;
            iS[et] = base; iD[et] = base + 1; iW_[et] = base + 2;
            iWm[et] = base + 3; iB[et] = base + 4;
        } else {
            iS[et] = 2 + et * 3; iD[et] = 3 + et * 3; iW_[et] = 4 + et * 3;
            iWm[et] = 17 + et * 2; iB[et] = 18 + et * 2;
        }
    }

    const float* feat_word  = (const float*)d_in[0];
    const float* feat_topic = (const float*)d_in[1];
    float* out = (float*)d_out;

    // 1) zero degrees
    zero_deg_kernel<<<dim3((N_WORD + 255) / 256, 5), 256>>>();

    // 2) histogram
    for (int et = 0; et < 5; et++)
        hist_kernel<<<(E_arr[et] + 255) / 256, 256>>>((const int*)d_in[iD[et]], et, E_arr[et]);

    // 3) scan
    for (int et = 0; et < 5; et++)
        scan_kernel<<<1, 1024>>>(et);

    // 4) fill sorted (src,w)
    for (int et = 0; et < 5; et++)
        fill_kernel<<<(E_arr[et] + 255) / 256, 256>>>(
            (const int*)d_in[iS[et]], (const int*)d_in[iD[et]],
            (const float*)d_in[iW_[et]], et, E_arr[et]);

    // 5) GEMMs (independent of CSR build; same stream is fine)
    for (int et = 0; et < 5; et++) {
        const float* A = (et < 3) ? feat_word : feat_topic;
        int M = (et < 3) ? N_WORD : N_TOPIC;
        gemm_kernel<<<(M + 127) / 128, 256>>>(
            A, (const float*)d_in[iWm[et]], (const float*)d_in[iB[et]], et, M, D_IN);
    }

    // 6) aggregation: word = mean(ww); topic = mean(wt)+mean(tt); doc = mean(wd)+mean(td)
    agg_kernel<<<(N_WORD  * 32 + 255) / 256, 256>>>(out,                                   0, -1, N_WORD);
    agg_kernel<<<(N_TOPIC * 32 + 255) / 256, 256>>>(out + (size_t)N_WORD * D_OUT,          1,  4, N_TOPIC);
    agg_kernel<<<(N_DOC   * 32 + 255) / 256, 256>>>(out + (size_t)(N_WORD + N_TOPIC) * D_OUT, 2, 3, N_DOC);
    (void)NDST_arr;
}